// round 1
// baseline (speedup 1.0000x reference)
#include <cuda_runtime.h>
#include <cuda_bf16.h>

// DAS beamforming: out[b, m, k] = sum_c lerp(rf[b, c, :, k], s(b, m, c))
// B=2, Nc=128, Ns=2048, Nz*Nx=65536, K=4.
// One thread per pixel; loop over 128 channels; rf gathered as float4 rows.

namespace {
constexpr int NB = 2;
constexpr int NC = 128;
constexpr int NS = 2048;
constexpr int NZ = 256;
constexpr int NX = 256;
constexpr int KW = 4;
constexpr int M  = NZ * NX;             // 65536 pixels per batch
constexpr int THREADS = 256;
constexpr int BLOCKS_PER_B = M / THREADS;  // 256
}

__global__ __launch_bounds__(THREADS)
void das_beamform_kernel(const float* __restrict__ rf,
                         const float* __restrict__ g,
                         const float* __restrict__ pr,
                         const float* __restrict__ p,
                         float* __restrict__ out) {
    __shared__ float s_prx[NC];
    __shared__ float s_pry[NC];
    __shared__ float s_prz[NC];

    const int tid = threadIdx.x;
    const int b   = blockIdx.x / BLOCKS_PER_B;
    const int m   = (blockIdx.x % BLOCKS_PER_B) * THREADS + tid;

    // Stage receiver positions for this batch into smem (all threads in a
    // block share the same b).
    if (tid < NC) {
        const float* prb = pr + (size_t)b * NC * 3 + (size_t)tid * 3;
        s_prx[tid] = prb[0];
        s_pry[tid] = prb[1];
        s_prz[tid] = prb[2];
    }
    __syncthreads();

    // Acquisition params
    const float c0 = p[b * 4 + 0];
    const float fs = p[b * 4 + 1];
    const float t0 = p[b * 4 + 2];
    const float scale = fs / c0;             // samples per meter

    // Pixel coordinates
    const float* gp = g + ((size_t)b * M + m) * 3;
    const float gx = gp[0];
    const float gy = gp[1];
    const float gz = gp[2];

    // s = fs*(t0 + d_rx + d_tx)/c0 = base + scale * d_rx, with d_tx = gz.
    const float base = fs * t0 / c0 + scale * gz;

    const float4* rfb = reinterpret_cast<const float4*>(rf)
                      + (size_t)b * NC * NS;   // rf rows are float4 (K=4)

    float4 acc = make_float4(0.f, 0.f, 0.f, 0.f);

    #pragma unroll 4
    for (int c = 0; c < NC; ++c) {
        const float dx = gx - s_prx[c];
        const float dy = gy - s_pry[c];
        const float dz = gz - s_prz[c];
        float d2 = fmaf(dx, dx, fmaf(dy, dy, dz * dz));
        // d = sqrt(d2) via one MUFU (rsqrt) + mul; guard d2==0.
        const float drx = d2 * rsqrtf(fmaxf(d2, 1e-30f));

        float s = fmaf(scale, drx, base);
        s = fminf(fmaxf(s, 0.0f), (float)(NS - 1));
        int i0 = (int)s;                 // floor for s >= 0
        i0 = min(i0, NS - 2);
        const float w = s - (float)i0;

        const float4* row = rfb + (size_t)c * NS + i0;
        const float4 y0 = row[0];
        const float4 y1 = row[1];

        acc.x = fmaf(w, y1.x - y0.x, acc.x + y0.x);
        acc.y = fmaf(w, y1.y - y0.y, acc.y + y0.y);
        acc.z = fmaf(w, y1.z - y0.z, acc.z + y0.z);
        acc.w = fmaf(w, y1.w - y0.w, acc.w + y0.w);
    }

    reinterpret_cast<float4*>(out)[(size_t)b * M + m] = acc;
}

extern "C" void kernel_launch(void* const* d_in, const int* in_sizes, int n_in,
                              void* d_out, int out_size) {
    const float* rf = (const float*)d_in[0];  // [B, Nc, Ns, K]
    const float* g  = (const float*)d_in[1];  // [B, Nz, Nx, 3]
    const float* pr = (const float*)d_in[2];  // [B, Nc, 3]
    const float* p  = (const float*)d_in[3];  // [B, 4]
    float* out = (float*)d_out;               // [B, Nz, Nx, K]

    dim3 grid(NB * BLOCKS_PER_B);             // 512 blocks
    dim3 block(THREADS);
    das_beamform_kernel<<<grid, block>>>(rf, g, pr, p, out);
}

// round 2
// speedup vs baseline: 1.2750x; 1.2750x over previous
#include <cuda_runtime.h>
#include <cuda_bf16.h>
#include <cstdint>

// DAS beamforming, smem-staged gather version.
// out[b, m, k] = sum_c lerp(rf[b, c, :, k], s(b, m, c))
// B=2, Nc=128, Ns=2048, M=Nz*Nx=65536, K=4.
//
// Each block: (batch, 2048-pixel tile, 16-channel group).
// Per channel: stage rf[b,c,:,:] (32KB) into double-buffered smem via
// cp.async, then every thread gathers (y0,y1) float4 pairs from smem for its
// 8 register-resident pixels. Channel-group partials combined via atomicAdd
// into a zeroed output.

namespace {
constexpr int NB = 2;
constexpr int NC = 128;
constexpr int NS = 2048;
constexpr int M  = 65536;          // Nz*Nx per batch
constexpr int THREADS = 256;
constexpr int PXT = 8;             // pixels per thread
constexpr int TILE_P = THREADS * PXT;    // 2048
constexpr int TILES = M / TILE_P;        // 32
constexpr int CPG = 16;            // channels per group
constexpr int NG  = NC / CPG;      // 8
constexpr int SMEM_BYTES = 2 * NS * 16;  // double buffer of float4 rows = 64KB
}

__device__ __forceinline__ void cp_async16(uint32_t smem_addr, const void* gptr) {
    asm volatile("cp.async.cg.shared.global [%0], [%1], 16;\n"
                 :: "r"(smem_addr), "l"(gptr) : "memory");
}
__device__ __forceinline__ void cp_async_commit() {
    asm volatile("cp.async.commit_group;\n" ::: "memory");
}
template <int N>
__device__ __forceinline__ void cp_async_wait() {
    asm volatile("cp.async.wait_group %0;\n" :: "n"(N) : "memory");
}

__global__ __launch_bounds__(THREADS, 2)
void das_stage_kernel(const float* __restrict__ rf,
                      const float* __restrict__ g,
                      const float* __restrict__ pr,
                      const float* __restrict__ p,
                      float* __restrict__ out) {
    extern __shared__ float4 sbuf[];            // [2][NS] float4
    __shared__ float sprx[CPG], spry[CPG], sprz[CPG];

    const int tid  = threadIdx.x;
    int idx = blockIdx.x;
    const int b    = idx / (TILES * NG);
    idx -= b * (TILES * NG);
    const int tile = idx / NG;
    const int grp  = idx - tile * NG;
    const int c0   = grp * CPG;
    const int pm   = tile * TILE_P;             // first pixel of tile

    // Receiver positions for this channel group.
    if (tid < CPG) {
        const float* prb = pr + ((size_t)b * NC + (c0 + tid)) * 3;
        sprx[tid] = prb[0];
        spry[tid] = prb[1];
        sprz[tid] = prb[2];
    }

    // Acquisition params.
    const float c0s = p[b * 4 + 0];
    const float fs  = p[b * 4 + 1];
    const float t0  = p[b * 4 + 2];
    const float scale = fs / c0s;
    const float tbase = fs * t0 / c0s;

    // Per-pixel registers.
    float gx[PXT], gy[PXT], gz[PXT], base[PXT];
    float4 acc[PXT];
    #pragma unroll
    for (int j = 0; j < PXT; ++j) {
        const int m = pm + tid + j * THREADS;
        const float* gp = g + ((size_t)b * M + m) * 3;
        gx[j] = gp[0];
        gy[j] = gp[1];
        gz[j] = gp[2];
        base[j] = fmaf(scale, gz[j], tbase);    // tx path = depth
        acc[j] = make_float4(0.f, 0.f, 0.f, 0.f);
    }

    const float4* rfb = reinterpret_cast<const float4*>(rf) + (size_t)b * NC * NS;

    const uint32_t sbase = (uint32_t)__cvta_generic_to_shared(sbuf);

    // Stage channel c into buffer buf. Each thread copies 8 float4 (128B).
    auto stage = [&](int c, int buf) {
        const float4* src = rfb + (size_t)c * NS;
        uint32_t dst = sbase + (uint32_t)buf * NS * 16;
        #pragma unroll
        for (int j = 0; j < NS / THREADS; ++j) {
            const int e = tid + j * THREADS;
            cp_async16(dst + e * 16, src + e);
        }
        cp_async_commit();
    };

    stage(c0, 0);

    for (int k = 0; k < CPG; ++k) {
        if (k + 1 < CPG) {
            stage(c0 + k + 1, (k + 1) & 1);
            cp_async_wait<1>();
        } else {
            cp_async_wait<0>();
        }
        __syncthreads();

        const float4* cur = sbuf + (k & 1) * NS;
        const float prx = sprx[k];
        const float pry = spry[k];
        const float prz = sprz[k];

        #pragma unroll
        for (int j = 0; j < PXT; ++j) {
            const float dx = gx[j] - prx;
            const float dy = gy[j] - pry;
            const float dz = gz[j] - prz;
            float d2 = fmaf(dx, dx, fmaf(dy, dy, dz * dz));
            const float drx = d2 * rsqrtf(fmaxf(d2, 1e-30f));

            float s = fmaf(scale, drx, base[j]);
            s = fminf(fmaxf(s, 0.0f), (float)(NS - 1));
            int i0 = min((int)s, NS - 2);
            const float w = s - (float)i0;

            const float4 y0 = cur[i0];
            const float4 y1 = cur[i0 + 1];

            acc[j].x = fmaf(w, y1.x - y0.x, acc[j].x + y0.x);
            acc[j].y = fmaf(w, y1.y - y0.y, acc[j].y + y0.y);
            acc[j].z = fmaf(w, y1.z - y0.z, acc[j].z + y0.z);
            acc[j].w = fmaf(w, y1.w - y0.w, acc[j].w + y0.w);
        }
        __syncthreads();   // buffer (k&1) may be re-staged next iteration
    }

    // Combine channel-group partials.
    #pragma unroll
    for (int j = 0; j < PXT; ++j) {
        const int m = pm + tid + j * THREADS;
        float* o = out + ((size_t)b * M + m) * 4;
        atomicAdd(o + 0, acc[j].x);
        atomicAdd(o + 1, acc[j].y);
        atomicAdd(o + 2, acc[j].z);
        atomicAdd(o + 3, acc[j].w);
    }
}

extern "C" void kernel_launch(void* const* d_in, const int* in_sizes, int n_in,
                              void* d_out, int out_size) {
    const float* rf = (const float*)d_in[0];  // [B, Nc, Ns, K]
    const float* g  = (const float*)d_in[1];  // [B, Nz, Nx, 3]
    const float* pr = (const float*)d_in[2];  // [B, Nc, 3]
    const float* p  = (const float*)d_in[3];  // [B, 4]
    float* out = (float*)d_out;               // [B, Nz, Nx, K] floats

    cudaFuncSetAttribute(das_stage_kernel,
                         cudaFuncAttributeMaxDynamicSharedMemorySize, SMEM_BYTES);

    cudaMemsetAsync(out, 0, (size_t)out_size * sizeof(float));

    dim3 grid(NB * TILES * NG);   // 512 blocks
    dim3 block(THREADS);
    das_stage_kernel<<<grid, block, SMEM_BYTES>>>(rf, g, pr, p, out);
}

// round 3
// speedup vs baseline: 1.8995x; 1.4898x over previous
#include <cuda_runtime.h>
#include <cuda_fp16.h>
#include <cstdint>

// DAS beamforming, fp16-staged smem gather version.
// Pass 1: convert rf (fp32, 8MB, L2-resident) -> fp16 __device__ buffer (4MB).
// Pass 2: per block (batch, 2048-pixel tile, 16-channel group): double-buffer
// each channel's fp16 row (16KB) into smem via cp.async, gather y0/y1 as
// 8B LDS, lerp in fp32, combine group partials with red.global.add.v4.f32.

namespace {
constexpr int NB = 2;
constexpr int NC = 128;
constexpr int NS = 2048;
constexpr int M  = 65536;                 // Nz*Nx per batch
constexpr int THREADS = 512;
constexpr int PXT = 4;                    // pixels per thread
constexpr int TILE_P = THREADS * PXT;     // 2048
constexpr int TILES = M / TILE_P;         // 32
constexpr int CPG = 16;                   // channels per group
constexpr int NG  = NC / CPG;             // 8
constexpr int ROW_BYTES = NS * 8;         // fp16 row: 2048 samples * 4 halves
constexpr int SMEM_BYTES = 2 * ROW_BYTES; // 32KB double buffer
constexpr int NSAMP = NB * NC * NS;       // 524288 samples
}

__device__ uint2 g_rf16[NSAMP];           // [B][Nc][Ns] x 4 halves = 4MB

__device__ __forceinline__ void cp_async16(uint32_t smem_addr, const void* gptr) {
    asm volatile("cp.async.cg.shared.global [%0], [%1], 16;\n"
                 :: "r"(smem_addr), "l"(gptr) : "memory");
}
__device__ __forceinline__ void cp_async_commit() {
    asm volatile("cp.async.commit_group;\n" ::: "memory");
}
template <int N>
__device__ __forceinline__ void cp_async_wait() {
    asm volatile("cp.async.wait_group %0;\n" :: "n"(N) : "memory");
}
__device__ __forceinline__ void red_add_v4(float* ptr, float4 v) {
    asm volatile("red.global.add.v4.f32 [%0], {%1, %2, %3, %4};\n"
                 :: "l"(ptr), "f"(v.x), "f"(v.y), "f"(v.z), "f"(v.w)
                 : "memory");
}

__global__ __launch_bounds__(256)
void rf_to_fp16_kernel(const float4* __restrict__ rf) {
    const int i = blockIdx.x * blockDim.x + threadIdx.x;
    if (i < NSAMP) {
        const float4 v = rf[i];
        const __half2 h0 = __float22half2_rn(make_float2(v.x, v.y));
        const __half2 h1 = __float22half2_rn(make_float2(v.z, v.w));
        uint2 u;
        u.x = *reinterpret_cast<const unsigned int*>(&h0);
        u.y = *reinterpret_cast<const unsigned int*>(&h1);
        g_rf16[i] = u;
    }
}

__global__ __launch_bounds__(THREADS, 2)
void das_fp16_kernel(const float* __restrict__ g,
                     const float* __restrict__ pr,
                     const float* __restrict__ p,
                     float* __restrict__ out) {
    extern __shared__ uint2 sbuf[];                 // [2][NS] samples (8B each)
    __shared__ float sprx[CPG], spry[CPG], sprz[CPG];

    const int tid  = threadIdx.x;
    int idx = blockIdx.x;
    const int b    = idx / (TILES * NG);
    idx -= b * (TILES * NG);
    const int tile = idx / NG;
    const int grp  = idx - tile * NG;
    const int c0   = grp * CPG;
    const int pm   = tile * TILE_P;

    if (tid < CPG) {
        const float* prb = pr + ((size_t)b * NC + (c0 + tid)) * 3;
        sprx[tid] = prb[0];
        spry[tid] = prb[1];
        sprz[tid] = prb[2];
    }

    const float c0s = p[b * 4 + 0];
    const float fs  = p[b * 4 + 1];
    const float t0  = p[b * 4 + 2];
    const float scale = fs / c0s;
    const float tbase = fs * t0 / c0s;

    float gx[PXT], gy[PXT], gz[PXT];
    float4 acc[PXT];
    #pragma unroll
    for (int j = 0; j < PXT; ++j) {
        const int m = pm + tid + j * THREADS;
        const float* gp = g + ((size_t)b * M + m) * 3;
        gx[j] = gp[0];
        gy[j] = gp[1];
        gz[j] = gp[2];
        acc[j] = make_float4(0.f, 0.f, 0.f, 0.f);
    }

    const uint2* rfb = g_rf16 + (size_t)b * NC * NS;
    const uint32_t sbase = (uint32_t)__cvta_generic_to_shared(sbuf);

    // Stage channel c (16KB) into buffer buf: 1024 x 16B chunks, 2 per thread.
    auto stage = [&](int c, int buf) {
        const uint2* src = rfb + (size_t)c * NS;
        const uint32_t dst = sbase + (uint32_t)buf * ROW_BYTES;
        #pragma unroll
        for (int j = 0; j < NS / 2 / THREADS; ++j) {   // 2 iters
            const int e = tid + j * THREADS;           // 16B chunk index
            cp_async16(dst + e * 16, src + e * 2);
        }
        cp_async_commit();
    };

    stage(c0, 0);

    for (int k = 0; k < CPG; ++k) {
        if (k + 1 < CPG) {
            stage(c0 + k + 1, (k + 1) & 1);
            cp_async_wait<1>();
        } else {
            cp_async_wait<0>();
        }
        __syncthreads();

        const uint2* cur = sbuf + (k & 1) * NS;
        const float prx = sprx[k];
        const float pry = spry[k];
        const float prz = sprz[k];

        #pragma unroll
        for (int j = 0; j < PXT; ++j) {
            const float dx = gx[j] - prx;
            const float dy = gy[j] - pry;
            const float dz = gz[j] - prz;
            float d2 = fmaf(dx, dx, fmaf(dy, dy, dz * dz));
            const float drx = d2 * rsqrtf(fmaxf(d2, 1e-30f));

            float s = fmaf(scale, drx + gz[j], tbase);
            s = fminf(fmaxf(s, 0.0f), (float)(NS - 1));
            int i0 = min((int)s, NS - 2);
            const float w = s - (float)i0;
            const float omw = 1.0f - w;

            const uint2 v0 = cur[i0];
            const uint2 v1 = cur[i0 + 1];

            const float2 a0 = __half22float2(*reinterpret_cast<const __half2*>(&v0.x));
            const float2 a1 = __half22float2(*reinterpret_cast<const __half2*>(&v0.y));
            const float2 b0 = __half22float2(*reinterpret_cast<const __half2*>(&v1.x));
            const float2 b1 = __half22float2(*reinterpret_cast<const __half2*>(&v1.y));

            acc[j].x = fmaf(a0.x, omw, fmaf(b0.x, w, acc[j].x));
            acc[j].y = fmaf(a0.y, omw, fmaf(b0.y, w, acc[j].y));
            acc[j].z = fmaf(a1.x, omw, fmaf(b1.x, w, acc[j].z));
            acc[j].w = fmaf(a1.y, omw, fmaf(b1.y, w, acc[j].w));
        }
        __syncthreads();
    }

    #pragma unroll
    for (int j = 0; j < PXT; ++j) {
        const int m = pm + tid + j * THREADS;
        red_add_v4(out + ((size_t)b * M + m) * 4, acc[j]);
    }
}

extern "C" void kernel_launch(void* const* d_in, const int* in_sizes, int n_in,
                              void* d_out, int out_size) {
    const float* rf = (const float*)d_in[0];  // [B, Nc, Ns, K]
    const float* g  = (const float*)d_in[1];  // [B, Nz, Nx, 3]
    const float* pr = (const float*)d_in[2];  // [B, Nc, 3]
    const float* p  = (const float*)d_in[3];  // [B, 4]
    float* out = (float*)d_out;               // [B, Nz, Nx, K]

    cudaFuncSetAttribute(das_fp16_kernel,
                         cudaFuncAttributeMaxDynamicSharedMemorySize, SMEM_BYTES);

    // Pass 1: rf -> fp16
    rf_to_fp16_kernel<<<(NSAMP + 255) / 256, 256>>>(
        reinterpret_cast<const float4*>(rf));

    // Zero output for atomic accumulation.
    cudaMemsetAsync(out, 0, (size_t)out_size * sizeof(float));

    // Pass 2: beamform
    dim3 grid(NB * TILES * NG);   // 512 blocks
    das_fp16_kernel<<<grid, THREADS, SMEM_BYTES>>>(g, pr, p, out);
}

// round 4
// speedup vs baseline: 1.9266x; 1.0143x over previous
#include <cuda_runtime.h>
#include <cuda_fp16.h>
#include <cstdint>

// DAS beamforming, fp16-staged smem gather, 4-deep cp.async pipeline.
// Pass 1: convert rf (fp32, 8MB, L2-resident) -> fp16 __device__ buffer (4MB).
// Pass 2: per block (batch, 2048-pixel tile, 16-channel group): pipeline each
// channel's fp16 row (16KB) through a 4-buffer smem ring via cp.async (one
// __syncthreads per channel), gather y0/y1 as 8B LDS, lerp in fp32, combine
// group partials with red.global.add.v4.f32.

namespace {
constexpr int NB = 2;
constexpr int NC = 128;
constexpr int NS = 2048;
constexpr int M  = 65536;                 // Nz*Nx per batch
constexpr int THREADS = 512;
constexpr int PXT = 4;                    // pixels per thread
constexpr int TILE_P = THREADS * PXT;     // 2048
constexpr int TILES = M / TILE_P;         // 32
constexpr int CPG = 16;                   // channels per group
constexpr int NG  = NC / CPG;             // 8
constexpr int ROW_BYTES = NS * 8;         // fp16 row: 2048 samples * 8B
constexpr int NBUF = 4;
constexpr int SMEM_BYTES = NBUF * ROW_BYTES;   // 64KB ring
constexpr int NSAMP = NB * NC * NS;       // 524288 samples
}

__device__ uint2 g_rf16[NSAMP];           // [B][Nc][Ns] x 4 halves = 4MB

__device__ __forceinline__ void cp_async16(uint32_t smem_addr, const void* gptr) {
    asm volatile("cp.async.cg.shared.global [%0], [%1], 16;\n"
                 :: "r"(smem_addr), "l"(gptr) : "memory");
}
__device__ __forceinline__ void cp_async_commit() {
    asm volatile("cp.async.commit_group;\n" ::: "memory");
}
template <int N>
__device__ __forceinline__ void cp_async_wait() {
    asm volatile("cp.async.wait_group %0;\n" :: "n"(N) : "memory");
}
__device__ __forceinline__ void red_add_v4(float* ptr, float4 v) {
    asm volatile("red.global.add.v4.f32 [%0], {%1, %2, %3, %4};\n"
                 :: "l"(ptr), "f"(v.x), "f"(v.y), "f"(v.z), "f"(v.w)
                 : "memory");
}

__global__ __launch_bounds__(256)
void rf_to_fp16_kernel(const float4* __restrict__ rf) {
    const int i = blockIdx.x * blockDim.x + threadIdx.x;
    if (i < NSAMP) {
        const float4 v = rf[i];
        const __half2 h0 = __float22half2_rn(make_float2(v.x, v.y));
        const __half2 h1 = __float22half2_rn(make_float2(v.z, v.w));
        uint2 u;
        u.x = *reinterpret_cast<const unsigned int*>(&h0);
        u.y = *reinterpret_cast<const unsigned int*>(&h1);
        g_rf16[i] = u;
    }
}

__global__ __launch_bounds__(THREADS, 3)
void das_fp16_kernel(const float* __restrict__ g,
                     const float* __restrict__ pr,
                     const float* __restrict__ p,
                     float* __restrict__ out) {
    extern __shared__ uint2 sbuf[];                 // [NBUF][NS] samples
    __shared__ float sprx[CPG], spry[CPG], sprz[CPG];

    const int tid  = threadIdx.x;
    int idx = blockIdx.x;
    const int b    = idx / (TILES * NG);
    idx -= b * (TILES * NG);
    const int tile = idx / NG;
    const int grp  = idx - tile * NG;
    const int c0   = grp * CPG;
    const int pm   = tile * TILE_P;

    if (tid < CPG) {
        const float* prb = pr + ((size_t)b * NC + (c0 + tid)) * 3;
        sprx[tid] = prb[0];
        spry[tid] = prb[1];
        sprz[tid] = prb[2];
    }

    const float c0s = p[b * 4 + 0];
    const float fs  = p[b * 4 + 1];
    const float t0  = p[b * 4 + 2];
    const float scale = fs / c0s;
    const float tbase = fs * t0 / c0s;

    float gx[PXT], gy[PXT], gz[PXT];
    float4 acc[PXT];
    #pragma unroll
    for (int j = 0; j < PXT; ++j) {
        const int m = pm + tid + j * THREADS;
        const float* gp = g + ((size_t)b * M + m) * 3;
        gx[j] = gp[0];
        gy[j] = gp[1];
        gz[j] = gp[2];
        acc[j] = make_float4(0.f, 0.f, 0.f, 0.f);
    }

    const uint2* rfb = g_rf16 + (size_t)b * NC * NS;
    const uint32_t sbase = (uint32_t)__cvta_generic_to_shared(sbuf);

    // Stage one fp16 channel row (16KB) into ring buffer `buf`.
    auto stage = [&](int c, int buf) {
        const uint2* src = rfb + (size_t)c * NS;
        const uint32_t dst = sbase + (uint32_t)buf * ROW_BYTES;
        #pragma unroll
        for (int j = 0; j < NS / 2 / THREADS; ++j) {   // 2 iters of 16B chunks
            const int e = tid + j * THREADS;
            cp_async16(dst + e * 16, src + e * 2);
        }
    };

    // Prologue: stage channels 0..2 as groups g0..g2.
    stage(c0 + 0, 0); cp_async_commit();
    stage(c0 + 1, 1); cp_async_commit();
    stage(c0 + 2, 2); cp_async_commit();

    for (int k = 0; k < CPG; ++k) {
        // All warps done reading buffer (k+3)%4 (== (k-1)%4) before restaging.
        // For k==0 this also orders the spr* smem writes.
        __syncthreads();

        if (k + 3 < CPG) stage(c0 + k + 3, (k + 3) & (NBUF - 1));
        cp_async_commit();          // exactly one group per iteration

        // Committed groups: g0..g_{k+3}. Leave 3 in flight -> g_k complete.
        cp_async_wait<3>();

        const uint2* cur = sbuf + (size_t)(k & (NBUF - 1)) * NS;
        const float prx = sprx[k];
        const float pry = spry[k];
        const float prz = sprz[k];

        #pragma unroll
        for (int j = 0; j < PXT; ++j) {
            const float dx = gx[j] - prx;
            const float dy = gy[j] - pry;
            const float dz = gz[j] - prz;
            float d2 = fmaf(dx, dx, fmaf(dy, dy, dz * dz));
            const float drx = d2 * rsqrtf(fmaxf(d2, 1e-30f));

            float s = fmaf(scale, drx + gz[j], tbase);
            s = fminf(fmaxf(s, 0.0f), (float)(NS - 1));
            int i0 = min((int)s, NS - 2);
            const float w = s - (float)i0;
            const float omw = 1.0f - w;

            const uint2 v0 = cur[i0];
            const uint2 v1 = cur[i0 + 1];

            const float2 a0 = __half22float2(*reinterpret_cast<const __half2*>(&v0.x));
            const float2 a1 = __half22float2(*reinterpret_cast<const __half2*>(&v0.y));
            const float2 b0 = __half22float2(*reinterpret_cast<const __half2*>(&v1.x));
            const float2 b1 = __half22float2(*reinterpret_cast<const __half2*>(&v1.y));

            acc[j].x = fmaf(a0.x, omw, fmaf(b0.x, w, acc[j].x));
            acc[j].y = fmaf(a0.y, omw, fmaf(b0.y, w, acc[j].y));
            acc[j].z = fmaf(a1.x, omw, fmaf(b1.x, w, acc[j].z));
            acc[j].w = fmaf(a1.y, omw, fmaf(b1.y, w, acc[j].w));
        }
    }

    #pragma unroll
    for (int j = 0; j < PXT; ++j) {
        const int m = pm + tid + j * THREADS;
        red_add_v4(out + ((size_t)b * M + m) * 4, acc[j]);
    }
}

extern "C" void kernel_launch(void* const* d_in, const int* in_sizes, int n_in,
                              void* d_out, int out_size) {
    const float* rf = (const float*)d_in[0];  // [B, Nc, Ns, K]
    const float* g  = (const float*)d_in[1];  // [B, Nz, Nx, 3]
    const float* pr = (const float*)d_in[2];  // [B, Nc, 3]
    const float* p  = (const float*)d_in[3];  // [B, 4]
    float* out = (float*)d_out;               // [B, Nz, Nx, K]

    cudaFuncSetAttribute(das_fp16_kernel,
                         cudaFuncAttributeMaxDynamicSharedMemorySize, SMEM_BYTES);

    // Pass 1: rf -> fp16
    rf_to_fp16_kernel<<<(NSAMP + 255) / 256, 256>>>(
        reinterpret_cast<const float4*>(rf));

    // Zero output for atomic accumulation.
    cudaMemsetAsync(out, 0, (size_t)out_size * sizeof(float));

    // Pass 2: beamform
    dim3 grid(NB * TILES * NG);   // 512 blocks
    das_fp16_kernel<<<grid, THREADS, SMEM_BYTES>>>(g, pr, p, out);
}